// round 14
// baseline (speedup 1.0000x reference)
#include <cuda_runtime.h>
#include <cuda_fp16.h>
#include <cstdint>
#include <math.h>

// ---------------- problem constants ----------------
#define Bb 2048
#define Kk 100000
#define Dd 50
#define BM 64
#define BN 128
#define SPLIT 9
#define NCHUNKS ((Kk + BN - 1) / BN)     // 782

// split-K partial scratch
__device__ float g_pu[(size_t)SPLIT * Bb * Dd];
__device__ float g_pden[SPLIT * Bb];
// pre-swizzled fp16 HI images of M: 16 KB per chunk
// HI rows: [mh(0..49), 0(50..55), mh48, mh49, ml48, ml49, 0(60..63)]
__device__ __align__(16) unsigned char g_img[(size_t)NCHUNKS * 16384];

// smem layout (bytes): x tiles 8 KB each, two 16 KB chunk buffers
#define SM_XH 0
#define SM_XL 8192
#define SM_B0 16384
#define SM_B1 32768
#define SM_TOTAL 49152

#define SWZ(o) ((o) ^ (((o) >> 3) & 0x70))

__device__ __forceinline__ uint32_t smem_u32(const void* p) {
    uint32_t a;
    asm("{ .reg .u64 t; cvta.to.shared.u64 t, %1; cvt.u32.u64 %0, t; }" : "=r"(a) : "l"(p));
    return a;
}
__device__ __forceinline__ void ldsm4(uint32_t addr, uint32_t r[4]) {
    asm volatile("ldmatrix.sync.aligned.m8n8.x4.shared.b16 {%0,%1,%2,%3}, [%4];"
                 : "=r"(r[0]), "=r"(r[1]), "=r"(r[2]), "=r"(r[3]) : "r"(addr));
}
__device__ __forceinline__ void ldsm4t(uint32_t addr, uint32_t r[4]) {
    asm volatile("ldmatrix.sync.aligned.m8n8.x4.trans.shared.b16 {%0,%1,%2,%3}, [%4];"
                 : "=r"(r[0]), "=r"(r[1]), "=r"(r[2]), "=r"(r[3]) : "r"(addr));
}
// fp16 MMA, fp32 accumulate
__device__ __forceinline__ void mma16816h(float c[4], const uint32_t a[4],
                                          uint32_t b0, uint32_t b1) {
    asm volatile("mma.sync.aligned.m16n8k16.row.col.f32.f16.f16.f32 "
                 "{%0,%1,%2,%3}, {%4,%5,%6,%7}, {%8,%9}, {%0,%1,%2,%3};"
                 : "+f"(c[0]), "+f"(c[1]), "+f"(c[2]), "+f"(c[3])
                 : "r"(a[0]), "r"(a[1]), "r"(a[2]), "r"(a[3]), "r"(b0), "r"(b1));
}
__device__ __forceinline__ uint32_t packh2(float a, float b) {
    __half2 h = __floats2half2_rn(a, b);
    return *reinterpret_cast<uint32_t*>(&h);
}
__device__ __forceinline__ void copy_chunk_async256(uint32_t dst, const unsigned char* src, int tid) {
#pragma unroll
    for (int j = 0; j < 4; j++) {      // 16 KB / 256 threads = 64 B
        uint32_t off = (uint32_t)tid * 16 + j * 4096;
        asm volatile("cp.async.cg.shared.global [%0], [%1], 16;"
                     :: "r"(dst + off), "l"(src + off) : "memory");
    }
}

// ============ prep: M -> fp16 HI pre-swizzled chunk images (16 KB/chunk) ============
__global__ void prep_kernel(const float* __restrict__ M) {
    int chunk = blockIdx.x;
    size_t base = (size_t)chunk * 16384;
    for (int e = threadIdx.x; e < 128 * 8; e += 256) {
        int s = e >> 3, dg = e & 7;
        int slot = chunk * 128 + s;
        uint32_t key = (uint32_t)((s & 7) << 4);
        ushort hi[8];
        if (dg == 7) {
            float m48 = 0.f, m49 = 0.f;
            if (slot < Kk) {
                m48 = M[(size_t)slot * Dd + 48];
                m49 = M[(size_t)slot * Dd + 49];
            }
            __half h48 = __float2half_rn(m48);
            __half l48 = __float2half_rn(m48 - __half2float(h48));
            __half h49 = __float2half_rn(m49);
            __half l49 = __float2half_rn(m49 - __half2float(h49));
            hi[0] = __half_as_ushort(h48);
            hi[1] = __half_as_ushort(h49);
            hi[2] = __half_as_ushort(l48);
            hi[3] = __half_as_ushort(l49);
            hi[4] = hi[5] = hi[6] = hi[7] = 0;
        } else {
#pragma unroll
            for (int q = 0; q < 8; q++) {
                int d = 8 * dg + q;
                float v = (slot < Kk && d < Dd) ? M[(size_t)slot * Dd + d] : 0.f;
                hi[q] = __half_as_ushort(__float2half_rn(v));
            }
        }
        uint32_t off = (uint32_t)(s * 128) + (((uint32_t)(16 * dg)) ^ key);
        *reinterpret_cast<uint4*>(g_img + base + off) = *reinterpret_cast<uint4*>(hi);
    }
}

// =====================================================================
__global__ __launch_bounds__(256, 2)
void attn_mma_kernel(const float* __restrict__ x) {
    extern __shared__ __align__(1024) char smem[];
    const uint32_t sb = smem_u32(smem);
    const int tid = threadIdx.x;
    const int wid = tid >> 5;
    const int lane = tid & 31;
    const int wr = wid >> 1;        // row group (16 rows), 0..3
    const int wc = wid & 1;         // chunk half (64 slots)
    const int row0 = blockIdx.x * BM;
    const int split = blockIdx.y;
    const int chunk0 = (split * NCHUNKS) / SPLIT;
    const int chunk1 = ((split + 1) * NCHUNKS) / SPLIT;
    const int nch = chunk1 - chunk0;
    const int kb = chunk0 * BN;
    const int ke = min(Kk, chunk1 * BN);

    // zero x tiles (16 KB)
    for (int i = tid; i < 16384 / 4; i += 256)
        reinterpret_cast<uint32_t*>(smem)[i] = 0;
    __syncthreads();

    // x tile -> fp16 hi/lo, SW128 [row][dim]
    for (int e = tid; e < BM * Dd; e += 256) {
        int r = e / Dd, d = e - r * Dd;
        float v = x[(size_t)(row0 + r) * Dd + d];
        __half h = __float2half_rn(v);
        __half l = __float2half_rn(v - __half2float(h));
        uint32_t off = (uint32_t)(r * 128 + d * 2), sw = SWZ(off);
        *reinterpret_cast<__half*>(smem + SM_XH + sw) = h;
        *reinterpret_cast<__half*>(smem + SM_XL + sw) = l;
    }
    // xh dims 56..59 payload: [xl48, xl49, xh48, xh49]
    if (tid < BM) {
        int r = tid;
        float v48 = x[(size_t)(row0 + r) * Dd + 48];
        float v49 = x[(size_t)(row0 + r) * Dd + 49];
        __half h48 = __float2half_rn(v48);
        __half l48 = __float2half_rn(v48 - __half2float(h48));
        __half h49 = __float2half_rn(v49);
        __half l49 = __float2half_rn(v49 - __half2float(h49));
        ushort pay[4] = { __half_as_ushort(l48), __half_as_ushort(l49),
                          __half_as_ushort(h48), __half_as_ushort(h49) };
        uint32_t sw = SWZ((uint32_t)(r * 128 + 112));
        *reinterpret_cast<uint2*>(smem + SM_XH + sw) = *reinterpret_cast<uint2*>(pay);
    }

    copy_chunk_async256(sb + SM_B0, g_img + (size_t)chunk0 * 16384, tid);
    asm volatile("cp.async.commit_group;" ::: "memory");
    __syncthreads();

    // resident x A-frags: hi 4 k-steps (ks3 = payload), lo 3 k-steps
    uint32_t axh[4][4], axl[3][4];
    {
        int arow = wr * 16 + (lane & 15);
        int ahalf = (lane >> 4) & 1;
#pragma unroll
        for (int ks = 0; ks < 4; ks++) {
            uint32_t off = (uint32_t)(arow * 128 + ks * 32 + ahalf * 16);
            ldsm4(sb + SM_XH + SWZ(off), axh[ks]);
            if (ks < 3) ldsm4(sb + SM_XL + SWZ(off), axl[ks]);
        }
    }

    float u[7][4];
#pragma unroll
    for (int t = 0; t < 7; t++)
#pragma unroll
        for (int j = 0; j < 4; j++) u[t][j] = 0.f;
    float rs0 = 0.f, rs1 = 0.f;
    float mrun0 = -1e30f, mrun1 = -1e30f;

    const int brow = (lane & 7) + ((lane & 16) ? 8 : 0);
    const int bhalf = (lane >> 3) & 1;
    const int trow = (lane & 7) + ((lane & 8) ? 8 : 0);
    const int thalf = (lane >> 4) & 1;

    for (int i = 0; i < nch; i++) {
        const uint32_t mh = sb + ((i & 1) ? SM_B1 : SM_B0);
        const int nv = min(BN, ke - (kb + i * BN));

        if (i + 1 < nch)
            copy_chunk_async256(sb + ((i & 1) ? SM_B0 : SM_B1),
                                g_img + (size_t)(chunk0 + i + 1) * 16384, tid);
        asm volatile("cp.async.commit_group;" ::: "memory");
        asm volatile("cp.async.wait_group 1;" ::: "memory");
        __syncthreads();

#pragma unroll
        for (int s = 0; s < 4; s++) {
            const int st = 4 * wc + s;

            // GEMM1: (xh + xl)·Mh ; ks3 hi·hi (+ payload cross terms for dims 48/49)
            float c2[2][4];
#pragma unroll
            for (int h = 0; h < 2; h++)
#pragma unroll
                for (int j = 0; j < 4; j++) c2[h][j] = 0.f;
#pragma unroll
            for (int ks = 0; ks < 3; ks++) {
                uint32_t off = (uint32_t)((16 * st + brow) * 128 + ks * 32 + bhalf * 16);
                uint32_t bh[4];
                ldsm4(mh + SWZ(off), bh);
                mma16816h(c2[0], axh[ks], bh[0], bh[1]);
                mma16816h(c2[0], axl[ks], bh[0], bh[1]);
                mma16816h(c2[1], axh[ks], bh[2], bh[3]);
                mma16816h(c2[1], axl[ks], bh[2], bh[3]);
            }
            {
                uint32_t off = (uint32_t)((16 * st + brow) * 128 + 3 * 32 + bhalf * 16);
                uint32_t bh[4];
                ldsm4(mh + SWZ(off), bh);
                mma16816h(c2[0], axh[3], bh[0], bh[1]);
                mma16816h(c2[1], axh[3], bh[2], bh[3]);
            }

            // ---- online row max (uniform within each quad via shfl) ----
            float tmax0 = fmaxf(fmaxf(c2[0][0], c2[0][1]), fmaxf(c2[1][0], c2[1][1]));
            float tmax1 = fmaxf(fmaxf(c2[0][2], c2[0][3]), fmaxf(c2[1][2], c2[1][3]));
            tmax0 = fmaxf(tmax0, __shfl_xor_sync(0xffffffffu, tmax0, 1));
            tmax0 = fmaxf(tmax0, __shfl_xor_sync(0xffffffffu, tmax0, 2));
            tmax1 = fmaxf(tmax1, __shfl_xor_sync(0xffffffffu, tmax1, 1));
            tmax1 = fmaxf(tmax1, __shfl_xor_sync(0xffffffffu, tmax1, 2));
            if (tmax0 > mrun0) {
                float f = __expf(mrun0 - tmax0);
                rs0 *= f;
#pragma unroll
                for (int t = 0; t < 7; t++) { u[t][0] *= f; u[t][1] *= f; }
                mrun0 = tmax0;
            }
            if (tmax1 > mrun1) {
                float f = __expf(mrun1 - tmax1);
                rs1 *= f;
#pragma unroll
                for (int t = 0; t < 7; t++) { u[t][2] *= f; u[t][3] *= f; }
                mrun1 = tmax1;
            }

            // exp (offset, masked) + rowsum
            const int cb = 16 * st + 2 * (lane & 3);
            float q00 = (cb     < nv) ? __expf(c2[0][0] - mrun0) : 0.f;
            float q01 = (cb + 1 < nv) ? __expf(c2[0][1] - mrun0) : 0.f;
            float q02 = (cb     < nv) ? __expf(c2[0][2] - mrun1) : 0.f;
            float q03 = (cb + 1 < nv) ? __expf(c2[0][3] - mrun1) : 0.f;
            float q10 = (cb + 8 < nv) ? __expf(c2[1][0] - mrun0) : 0.f;
            float q11 = (cb + 9 < nv) ? __expf(c2[1][1] - mrun0) : 0.f;
            float q12 = (cb + 8 < nv) ? __expf(c2[1][2] - mrun1) : 0.f;
            float q13 = (cb + 9 < nv) ? __expf(c2[1][3] - mrun1) : 0.f;
            rs0 += q00 + q01 + q10 + q11;
            rs1 += q02 + q03 + q12 + q13;

            uint32_t pq[4];
            pq[0] = packh2(q00, q01);
            pq[1] = packh2(q02, q03);
            pq[2] = packh2(q10, q11);
            pq[3] = packh2(q12, q13);

            // GEMM2: u += P · Mh   (7 MMAs)
#pragma unroll
            for (int ep = 0; ep < 4; ep++) {
                uint32_t off = (uint32_t)((16 * st + trow) * 128 + ep * 32 + thalf * 16);
                uint32_t bh[4];
                ldsm4t(mh + SWZ(off), bh);
                mma16816h(u[2 * ep], pq, bh[0], bh[1]);
                if (ep < 3) {   // dims 56..63: payload/pad, skip
                    mma16816h(u[2 * ep + 1], pq, bh[2], bh[3]);
                }
            }
        }
        __syncthreads();
    }

    // ---- un-offset ----
    {
        float e0 = __expf(mrun0), e1 = __expf(mrun1);
        rs0 *= e0; rs1 *= e1;
#pragma unroll
        for (int t = 0; t < 7; t++) {
            u[t][0] *= e0; u[t][1] *= e0;
            u[t][2] *= e1; u[t][3] *= e1;
        }
    }

    // ---- rowsum reduce across the 4 lanes sharing a row ----
    rs0 += __shfl_xor_sync(0xffffffffu, rs0, 1);
    rs0 += __shfl_xor_sync(0xffffffffu, rs0, 2);
    rs1 += __shfl_xor_sync(0xffffffffu, rs1, 1);
    rs1 += __shfl_xor_sync(0xffffffffu, rs1, 2);

    // ---- cross-wc reduction through smem (x tiles dead; 64x64 f32 = 16 KB) ----
    __syncthreads();
    float* red = reinterpret_cast<float*>(smem);          // [64][64]
    float* redrs = red + 64 * 64;                         // [64] (into B0 region, dead)
    const int g = lane >> 2;

    if (wc == 1) {
#pragma unroll
        for (int t = 0; t < 7; t++) {
            int d0 = 8 * t + 2 * (lane & 3);
            red[(wr * 16 + g) * 64 + d0]     = u[t][0];
            red[(wr * 16 + g) * 64 + d0 + 1] = u[t][1];
            red[(wr * 16 + g + 8) * 64 + d0]     = u[t][2];
            red[(wr * 16 + g + 8) * 64 + d0 + 1] = u[t][3];
        }
        if ((lane & 3) == 0) {
            redrs[wr * 16 + g] = rs0;
            redrs[wr * 16 + g + 8] = rs1;
        }
    }
    __syncthreads();

    if (wc == 0) {
        const int r0 = row0 + wr * 16 + g;
        const int r1 = r0 + 8;
        rs0 += redrs[wr * 16 + g];
        rs1 += redrs[wr * 16 + g + 8];
        if ((lane & 3) == 0) {
            g_pden[split * Bb + r0] = rs0;
            g_pden[split * Bb + r1] = rs1;
        }
        size_t base0 = ((size_t)split * Bb + r0) * Dd;
        size_t base1 = ((size_t)split * Bb + r1) * Dd;
#pragma unroll
        for (int t = 0; t < 7; t++) {
            int d0 = 8 * t + 2 * (lane & 3);
            if (d0 < Dd) {
                g_pu[base0 + d0] = u[t][0] + red[(wr * 16 + g) * 64 + d0];
                g_pu[base1 + d0] = u[t][2] + red[(wr * 16 + g + 8) * 64 + d0];
                if (d0 + 1 < Dd) {
                    g_pu[base0 + d0 + 1] = u[t][1] + red[(wr * 16 + g) * 64 + d0 + 1];
                    g_pu[base1 + d0 + 1] = u[t][3] + red[(wr * 16 + g + 8) * 64 + d0 + 1];
                }
            }
        }
    }
}

// =====================================================================
__global__ void attn_combine_kernel(const float* __restrict__ x, float* __restrict__ out) {
    int b = blockIdx.x;
    int t = threadIdx.x;   // 64 threads
    if (t < Dd) {
        float den = 0.f, acc = 0.f;
#pragma unroll
        for (int s = 0; s < SPLIT; s++) {
            den += g_pden[s * Bb + b];
            acc += g_pu[((size_t)s * Bb + b) * Dd + t];
        }
        out[(size_t)b * (2 * Dd) + Dd + t] = acc / den;
        out[(size_t)b * (2 * Dd) + t] = x[(size_t)b * Dd + t];
    }
}

extern "C" void kernel_launch(void* const* d_in, const int* in_sizes, int n_in,
                              void* d_out, int out_size) {
    const float* x = (const float*)d_in[0];
    const float* M = (const float*)d_in[1];
    if (n_in >= 2 && in_sizes[0] == Kk * Dd && in_sizes[1] == Bb * Dd) {
        x = (const float*)d_in[1];
        M = (const float*)d_in[0];
    }
    float* out = (float*)d_out;

    cudaFuncSetAttribute(attn_mma_kernel,
                         cudaFuncAttributeMaxDynamicSharedMemorySize, SM_TOTAL);

    prep_kernel<<<NCHUNKS, 256>>>(M);
    attn_mma_kernel<<<dim3(Bb / BM, SPLIT), 256, SM_TOTAL>>>(x);
    attn_combine_kernel<<<Bb, 64>>>(x, out);
}

// round 17
// speedup vs baseline: 1.1399x; 1.1399x over previous
#include <cuda_runtime.h>
#include <cuda_fp16.h>
#include <cstdint>
#include <math.h>

// ---------------- problem constants ----------------
#define Bb 2048
#define Kk 100000
#define Dd 50
#define BM 128
#define BN 128
#define SPLIT 9
#define NCHUNKS ((Kk + BN - 1) / BN)     // 782

// split-K partial scratch
__device__ float g_pu[(size_t)SPLIT * Bb * Dd];
__device__ float g_pden[SPLIT * Bb];
// pre-swizzled fp16 HI images of M: 16 KB per chunk
// HI rows: [mh(0..49), 0(50..55), mh48, mh49, ml48, ml49, 0(60..63)]
__device__ __align__(16) unsigned char g_img[(size_t)NCHUNKS * 16384];

// smem layout (bytes): x hi tile 16 KB, two 16 KB chunk buffers
#define SM_XH 0
#define SM_B0 16384
#define SM_B1 32768
#define SM_TOTAL 49152

#define SWZ(o) ((o) ^ (((o) >> 3) & 0x70))

__device__ __forceinline__ uint32_t smem_u32(const void* p) {
    uint32_t a;
    asm("{ .reg .u64 t; cvta.to.shared.u64 t, %1; cvt.u32.u64 %0, t; }" : "=r"(a) : "l"(p));
    return a;
}
__device__ __forceinline__ void ldsm4(uint32_t addr, uint32_t r[4]) {
    asm volatile("ldmatrix.sync.aligned.m8n8.x4.shared.b16 {%0,%1,%2,%3}, [%4];"
                 : "=r"(r[0]), "=r"(r[1]), "=r"(r[2]), "=r"(r[3]) : "r"(addr));
}
__device__ __forceinline__ void ldsm4t(uint32_t addr, uint32_t r[4]) {
    asm volatile("ldmatrix.sync.aligned.m8n8.x4.trans.shared.b16 {%0,%1,%2,%3}, [%4];"
                 : "=r"(r[0]), "=r"(r[1]), "=r"(r[2]), "=r"(r[3]) : "r"(addr));
}
// fp16 MMA, fp32 accumulate
__device__ __forceinline__ void mma16816h(float c[4], const uint32_t a[4],
                                          uint32_t b0, uint32_t b1) {
    asm volatile("mma.sync.aligned.m16n8k16.row.col.f32.f16.f16.f32 "
                 "{%0,%1,%2,%3}, {%4,%5,%6,%7}, {%8,%9}, {%0,%1,%2,%3};"
                 : "+f"(c[0]), "+f"(c[1]), "+f"(c[2]), "+f"(c[3])
                 : "r"(a[0]), "r"(a[1]), "r"(a[2]), "r"(a[3]), "r"(b0), "r"(b1));
}
__device__ __forceinline__ uint32_t packh2(float a, float b) {
    __half2 h = __floats2half2_rn(a, b);
    return *reinterpret_cast<uint32_t*>(&h);
}
__device__ __forceinline__ void copy_chunk_async512(uint32_t dst, const unsigned char* src, int tid) {
#pragma unroll
    for (int j = 0; j < 2; j++) {      // 16 KB / 512 threads = 32 B
        uint32_t off = (uint32_t)tid * 16 + j * 8192;
        asm volatile("cp.async.cg.shared.global [%0], [%1], 16;"
                     :: "r"(dst + off), "l"(src + off) : "memory");
    }
}

// ============ prep: M -> fp16 HI pre-swizzled chunk images (16 KB/chunk) ============
__global__ void prep_kernel(const float* __restrict__ M) {
    int chunk = blockIdx.x;
    size_t base = (size_t)chunk * 16384;
    for (int e = threadIdx.x; e < 128 * 8; e += 256) {
        int s = e >> 3, dg = e & 7;
        int slot = chunk * 128 + s;
        uint32_t key = (uint32_t)((s & 7) << 4);
        ushort hi[8];
        if (dg == 7) {
            float m48 = 0.f, m49 = 0.f;
            if (slot < Kk) {
                m48 = M[(size_t)slot * Dd + 48];
                m49 = M[(size_t)slot * Dd + 49];
            }
            __half h48 = __float2half_rn(m48);
            __half l48 = __float2half_rn(m48 - __half2float(h48));
            __half h49 = __float2half_rn(m49);
            __half l49 = __float2half_rn(m49 - __half2float(h49));
            hi[0] = __half_as_ushort(h48);
            hi[1] = __half_as_ushort(h49);
            hi[2] = __half_as_ushort(l48);
            hi[3] = __half_as_ushort(l49);
            hi[4] = hi[5] = hi[6] = hi[7] = 0;
        } else {
#pragma unroll
            for (int q = 0; q < 8; q++) {
                int d = 8 * dg + q;
                float v = (slot < Kk && d < Dd) ? M[(size_t)slot * Dd + d] : 0.f;
                hi[q] = __half_as_ushort(__float2half_rn(v));
            }
        }
        uint32_t off = (uint32_t)(s * 128) + (((uint32_t)(16 * dg)) ^ key);
        *reinterpret_cast<uint4*>(g_img + base + off) = *reinterpret_cast<uint4*>(hi);
    }
}

// =====================================================================
__global__ __launch_bounds__(512, 1)
void attn_mma_kernel(const float* __restrict__ x) {
    extern __shared__ __align__(1024) char smem[];
    const uint32_t sb = smem_u32(smem);
    const int tid = threadIdx.x;
    const int wid = tid >> 5;
    const int lane = tid & 31;
    const int wr = wid >> 1;        // row group (16 rows)
    const int wc = wid & 1;         // chunk half (64 slots)
    const int row0 = blockIdx.x * BM;
    const int split = blockIdx.y;
    const int chunk0 = (split * NCHUNKS) / SPLIT;
    const int chunk1 = ((split + 1) * NCHUNKS) / SPLIT;
    const int nch = chunk1 - chunk0;
    const int kb = chunk0 * BN;
    const int ke = min(Kk, chunk1 * BN);

    // zero x hi tile (16 KB)
    for (int i = tid; i < 16384 / 4; i += 512)
        reinterpret_cast<uint32_t*>(smem)[i] = 0;
    __syncthreads();

    // x tile -> fp16 hi, SW128 [row][dim]
    for (int e = tid; e < BM * Dd; e += 512) {
        int r = e / Dd, d = e - r * Dd;
        float v = x[(size_t)(row0 + r) * Dd + d];
        uint32_t off = (uint32_t)(r * 128 + d * 2), sw = SWZ(off);
        *reinterpret_cast<__half*>(smem + SM_XH + sw) = __float2half_rn(v);
    }
    // xh dims 56..59 payload: [xl48, xl49, xh48, xh49]
    if (tid < BM) {
        int r = tid;
        float v48 = x[(size_t)(row0 + r) * Dd + 48];
        float v49 = x[(size_t)(row0 + r) * Dd + 49];
        __half h48 = __float2half_rn(v48);
        __half l48 = __float2half_rn(v48 - __half2float(h48));
        __half h49 = __float2half_rn(v49);
        __half l49 = __float2half_rn(v49 - __half2float(h49));
        ushort pay[4] = { __half_as_ushort(l48), __half_as_ushort(l49),
                          __half_as_ushort(h48), __half_as_ushort(h49) };
        uint32_t sw = SWZ((uint32_t)(r * 128 + 112));
        *reinterpret_cast<uint2*>(smem + SM_XH + sw) = *reinterpret_cast<uint2*>(pay);
    }

    copy_chunk_async512(sb + SM_B0, g_img + (size_t)chunk0 * 16384, tid);
    asm volatile("cp.async.commit_group;" ::: "memory");
    __syncthreads();

    // resident x A-frags: hi only, 4 k-steps (ks3 = payload)
    uint32_t axh[4][4];
    {
        int arow = wr * 16 + (lane & 15);
        int ahalf = (lane >> 4) & 1;
#pragma unroll
        for (int ks = 0; ks < 4; ks++) {
            uint32_t off = (uint32_t)(arow * 128 + ks * 32 + ahalf * 16);
            ldsm4(sb + SM_XH + SWZ(off), axh[ks]);
        }
    }

    float u[7][4];
#pragma unroll
    for (int t = 0; t < 7; t++)
#pragma unroll
        for (int j = 0; j < 4; j++) u[t][j] = 0.f;
    float rs0 = 0.f, rs1 = 0.f;
    float mrun0 = -1e30f, mrun1 = -1e30f;

    const int brow = (lane & 7) + ((lane & 16) ? 8 : 0);
    const int bhalf = (lane >> 3) & 1;
    const int trow = (lane & 7) + ((lane & 8) ? 8 : 0);
    const int thalf = (lane >> 4) & 1;

    for (int i = 0; i < nch; i++) {
        const uint32_t mh = sb + ((i & 1) ? SM_B1 : SM_B0);
        const int nv = min(BN, ke - (kb + i * BN));

        if (i + 1 < nch)
            copy_chunk_async512(sb + ((i & 1) ? SM_B0 : SM_B1),
                                g_img + (size_t)(chunk0 + i + 1) * 16384, tid);
        asm volatile("cp.async.commit_group;" ::: "memory");
        asm volatile("cp.async.wait_group 1;" ::: "memory");
        __syncthreads();

#pragma unroll
        for (int s = 0; s < 4; s++) {
            const int st = 4 * wc + s;

            // GEMM1: xh·Mh (ks0-2) ; ks3 payload (48/49 full split terms)
            float c2[2][4];
#pragma unroll
            for (int h = 0; h < 2; h++)
#pragma unroll
                for (int j = 0; j < 4; j++) c2[h][j] = 0.f;
#pragma unroll
            for (int ks = 0; ks < 4; ks++) {
                uint32_t off = (uint32_t)((16 * st + brow) * 128 + ks * 32 + bhalf * 16);
                uint32_t bh[4];
                ldsm4(mh + SWZ(off), bh);
                mma16816h(c2[0], axh[ks], bh[0], bh[1]);
                mma16816h(c2[1], axh[ks], bh[2], bh[3]);
            }

            // ---- online row max (uniform within each quad via shfl) ----
            float tmax0 = fmaxf(fmaxf(c2[0][0], c2[0][1]), fmaxf(c2[1][0], c2[1][1]));
            float tmax1 = fmaxf(fmaxf(c2[0][2], c2[0][3]), fmaxf(c2[1][2], c2[1][3]));
            tmax0 = fmaxf(tmax0, __shfl_xor_sync(0xffffffffu, tmax0, 1));
            tmax0 = fmaxf(tmax0, __shfl_xor_sync(0xffffffffu, tmax0, 2));
            tmax1 = fmaxf(tmax1, __shfl_xor_sync(0xffffffffu, tmax1, 1));
            tmax1 = fmaxf(tmax1, __shfl_xor_sync(0xffffffffu, tmax1, 2));
            if (tmax0 > mrun0) {
                float f = __expf(mrun0 - tmax0);
                rs0 *= f;
#pragma unroll
                for (int t = 0; t < 7; t++) { u[t][0] *= f; u[t][1] *= f; }
                mrun0 = tmax0;
            }
            if (tmax1 > mrun1) {
                float f = __expf(mrun1 - tmax1);
                rs1 *= f;
#pragma unroll
                for (int t = 0; t < 7; t++) { u[t][2] *= f; u[t][3] *= f; }
                mrun1 = tmax1;
            }

            // exp (offset, masked) + rowsum
            const int cb = 16 * st + 2 * (lane & 3);
            float q00 = (cb     < nv) ? __expf(c2[0][0] - mrun0) : 0.f;
            float q01 = (cb + 1 < nv) ? __expf(c2[0][1] - mrun0) : 0.f;
            float q02 = (cb     < nv) ? __expf(c2[0][2] - mrun1) : 0.f;
            float q03 = (cb + 1 < nv) ? __expf(c2[0][3] - mrun1) : 0.f;
            float q10 = (cb + 8 < nv) ? __expf(c2[1][0] - mrun0) : 0.f;
            float q11 = (cb + 9 < nv) ? __expf(c2[1][1] - mrun0) : 0.f;
            float q12 = (cb + 8 < nv) ? __expf(c2[1][2] - mrun1) : 0.f;
            float q13 = (cb + 9 < nv) ? __expf(c2[1][3] - mrun1) : 0.f;
            rs0 += q00 + q01 + q10 + q11;
            rs1 += q02 + q03 + q12 + q13;

            uint32_t pq[4];
            pq[0] = packh2(q00, q01);
            pq[1] = packh2(q02, q03);
            pq[2] = packh2(q10, q11);
            pq[3] = packh2(q12, q13);

            // GEMM2: u += P · Mh   (7 MMAs)
#pragma unroll
            for (int ep = 0; ep < 4; ep++) {
                uint32_t off = (uint32_t)((16 * st + trow) * 128 + ep * 32 + thalf * 16);
                uint32_t bh[4];
                ldsm4t(mh + SWZ(off), bh);
                mma16816h(u[2 * ep], pq, bh[0], bh[1]);
                if (ep < 3) {   // dims 56..63: payload/pad, skip
                    mma16816h(u[2 * ep + 1], pq, bh[2], bh[3]);
                }
            }
        }
        __syncthreads();
    }

    // ---- un-offset ----
    {
        float e0 = __expf(mrun0), e1 = __expf(mrun1);
        rs0 *= e0; rs1 *= e1;
#pragma unroll
        for (int t = 0; t < 7; t++) {
            u[t][0] *= e0; u[t][1] *= e0;
            u[t][2] *= e1; u[t][3] *= e1;
        }
    }

    // ---- rowsum reduce across the 4 lanes sharing a row ----
    rs0 += __shfl_xor_sync(0xffffffffu, rs0, 1);
    rs0 += __shfl_xor_sync(0xffffffffu, rs0, 2);
    rs1 += __shfl_xor_sync(0xffffffffu, rs1, 1);
    rs1 += __shfl_xor_sync(0xffffffffu, rs1, 2);

    // ---- cross-wc reduction through smem (x tile + B0 dead: 33 KB needed) ----
    __syncthreads();
    float* red = reinterpret_cast<float*>(smem);          // [128][64] = 32 KB
    float* redrs = red + 128 * 64;                        // [128]
    const int g = lane >> 2;

    if (wc == 1) {
#pragma unroll
        for (int t = 0; t < 7; t++) {
            int d0 = 8 * t + 2 * (lane & 3);
            red[(wr * 16 + g) * 64 + d0]     = u[t][0];
            red[(wr * 16 + g) * 64 + d0 + 1] = u[t][1];
            red[(wr * 16 + g + 8) * 64 + d0]     = u[t][2];
            red[(wr * 16 + g + 8) * 64 + d0 + 1] = u[t][3];
        }
        if ((lane & 3) == 0) {
            redrs[wr * 16 + g] = rs0;
            redrs[wr * 16 + g + 8] = rs1;
        }
    }
    __syncthreads();

    if (wc == 0) {
        const int r0 = row0 + wr * 16 + g;
        const int r1 = r0 + 8;
        rs0 += redrs[wr * 16 + g];
        rs1 += redrs[wr * 16 + g + 8];
        if ((lane & 3) == 0) {
            g_pden[split * Bb + r0] = rs0;
            g_pden[split * Bb + r1] = rs1;
        }
        size_t base0 = ((size_t)split * Bb + r0) * Dd;
        size_t base1 = ((size_t)split * Bb + r1) * Dd;
#pragma unroll
        for (int t = 0; t < 7; t++) {
            int d0 = 8 * t + 2 * (lane & 3);
            if (d0 < Dd) {
                g_pu[base0 + d0] = u[t][0] + red[(wr * 16 + g) * 64 + d0];
                g_pu[base1 + d0] = u[t][2] + red[(wr * 16 + g + 8) * 64 + d0];
                if (d0 + 1 < Dd) {
                    g_pu[base0 + d0 + 1] = u[t][1] + red[(wr * 16 + g) * 64 + d0 + 1];
                    g_pu[base1 + d0 + 1] = u[t][3] + red[(wr * 16 + g + 8) * 64 + d0 + 1];
                }
            }
        }
    }
}

// =====================================================================
__global__ void attn_combine_kernel(const float* __restrict__ x, float* __restrict__ out) {
    int b = blockIdx.x;
    int t = threadIdx.x;   // 64 threads
    if (t < Dd) {
        float den = 0.f, acc = 0.f;
#pragma unroll
        for (int s = 0; s < SPLIT; s++) {
            den += g_pden[s * Bb + b];
            acc += g_pu[((size_t)s * Bb + b) * Dd + t];
        }
        out[(size_t)b * (2 * Dd) + Dd + t] = acc / den;
        out[(size_t)b * (2 * Dd) + t] = x[(size_t)b * Dd + t];
    }
}

extern "C" void kernel_launch(void* const* d_in, const int* in_sizes, int n_in,
                              void* d_out, int out_size) {
    const float* x = (const float*)d_in[0];
    const float* M = (const float*)d_in[1];
    if (n_in >= 2 && in_sizes[0] == Kk * Dd && in_sizes[1] == Bb * Dd) {
        x = (const float*)d_in[1];
        M = (const float*)d_in[0];
    }
    float* out = (float*)d_out;

    cudaFuncSetAttribute(attn_mma_kernel,
                         cudaFuncAttributeMaxDynamicSharedMemorySize, SM_TOTAL);

    prep_kernel<<<NCHUNKS, 256>>>(M);
    attn_mma_kernel<<<dim3(Bb / BM, SPLIT), 512, SM_TOTAL>>>(x);
    attn_combine_kernel<<<Bb, 64>>>(x, out);
}